// round 2
// baseline (speedup 1.0000x reference)
#include <cuda_runtime.h>
#include <cstdint>

// VoxelHashTable: 2-level hash-grid trilinear interpolation.
// Inputs (metadata order):
//   d_in[0] query_pts (M,3) f32
//   d_in[1] feats0    (n0,32) f32
//   d_in[2] feats1    (n1,32) f32
//   d_in[3] h2v0      (2^20) i32
//   d_in[4] h2v1      (2^20) i32
// Output: (M, 64) f32  — [level0 32 | level1 32]

#define TSIZE_MASK ((1 << 20) - 1)
#define FDIM 32

// PRIMES % 2^20 (exact):
// 73856093 % 1048576 = 455773
// 19349669 % 1048576 = 475301
// 83492791 % 1048576 = 655287
#define PMX 455773
#define PMY 475301
#define PMZ 655287

__global__ __launch_bounds__(256) void voxel_hash_kernel(
    const float* __restrict__ q,
    const float* __restrict__ f0,
    const float* __restrict__ f1,
    const int* __restrict__ h0,
    const int* __restrict__ h1,
    float* __restrict__ out,
    int M)
{
    const int warp = (blockIdx.x * blockDim.x + threadIdx.x) >> 5;
    const int lane = threadIdx.x & 31;
    if (warp >= M) return;

    // Broadcast loads of the query point (same address across warp).
    const float qx = __ldg(q + warp * 3 + 0);
    const float qy = __ldg(q + warp * 3 + 1);
    const float qz = __ldg(q + warp * 3 + 2);

    // Level 0: res = 0.12f ; Level 1: res = 0.24f (exactly float32(0.12*2.0))
    // Use IEEE round-to-nearest division + floorf to bit-match the JAX f32 reference.
    const float s0x = __fdiv_rn(qx, 0.12f);
    const float s0y = __fdiv_rn(qy, 0.12f);
    const float s0z = __fdiv_rn(qz, 0.12f);
    const float s1x = __fdiv_rn(qx, 0.24f);
    const float s1y = __fdiv_rn(qy, 0.24f);
    const float s1z = __fdiv_rn(qz, 0.24f);

    const float b0x = floorf(s0x), b0y = floorf(s0y), b0z = floorf(s0z);
    const float b1x = floorf(s1x), b1y = floorf(s1y), b1z = floorf(s1z);

    const float fr0x = s0x - b0x, fr0y = s0y - b0y, fr0z = s0z - b0z;
    const float fr1x = s1x - b1x, fr1y = s1y - b1y, fr1z = s1z - b1z;

    const int i0x = (int)b0x, i0y = (int)b0y, i0z = (int)b0z;
    const int i1x = (int)b1x, i1y = (int)b1y, i1z = (int)b1z;

    // Lanes 0..7  : level 0 corners 0..7
    // Lanes 8..15 : level 1 corners 0..7
    // Each does one independent random 4B hash-table lookup.
    int vidx = -1;
    {
        const int lvl = lane >> 3;      // 0 or 1 (lanes < 16)
        const int c = lane & 7;
        const int ox = (c >> 2) & 1;    // OFFSETS: bit2=x, bit1=y, bit0=z
        const int oy = (c >> 1) & 1;
        const int oz = c & 1;
        const int cx = (lvl ? i1x : i0x) + ox;
        const int cy = (lvl ? i1y : i0y) + oy;
        const int cz = (lvl ? i1z : i0z) + oz;
        const unsigned hv =
            ((unsigned)(cx * PMX + cy * PMY + cz * PMZ)) & TSIZE_MASK;
        if (lane < 16) {
            vidx = lvl ? __ldg(h1 + hv) : __ldg(h0 + hv);
        }
    }

    // Accumulate both levels; lane = feature channel (coalesced 128B row reads).
    float acc0 = 0.0f;
    float acc1 = 0.0f;

    #pragma unroll
    for (int c = 0; c < 8; ++c) {
        const int ox = (c >> 2) & 1;
        const int oy = (c >> 1) & 1;
        const int oz = c & 1;

        // weight = prod over dims of (offset ? frac : 1-frac), matching
        // ((wx*wy)*wz) f32 order.
        const float w0 = (ox ? fr0x : 1.0f - fr0x) *
                         (oy ? fr0y : 1.0f - fr0y) *
                         (oz ? fr0z : 1.0f - fr0z);
        const float w1 = (ox ? fr1x : 1.0f - fr1x) *
                         (oy ? fr1y : 1.0f - fr1y) *
                         (oz ? fr1z : 1.0f - fr1z);

        const int v0 = __shfl_sync(0xFFFFFFFFu, vidx, c);
        const int v1 = __shfl_sync(0xFFFFFFFFu, vidx, c + 8);

        if (v0 >= 0) acc0 = fmaf(__ldg(f0 + (size_t)v0 * FDIM + lane), w0, acc0);
        if (v1 >= 0) acc1 = fmaf(__ldg(f1 + (size_t)v1 * FDIM + lane), w1, acc1);
    }

    out[(size_t)warp * 64 + lane] = acc0;
    out[(size_t)warp * 64 + 32 + lane] = acc1;
}

extern "C" void kernel_launch(void* const* d_in, const int* in_sizes, int n_in,
                              void* d_out, int out_size)
{
    const float* q  = (const float*)d_in[0];
    const float* f0 = (const float*)d_in[1];
    const float* f1 = (const float*)d_in[2];
    const int*   h0 = (const int*)d_in[3];
    const int*   h1 = (const int*)d_in[4];
    float* out = (float*)d_out;

    const int M = in_sizes[0] / 3;

    // 1 warp per query, 8 warps (256 threads) per block.
    const int warps_per_block = 8;
    const int blocks = (M + warps_per_block - 1) / warps_per_block;
    voxel_hash_kernel<<<blocks, warps_per_block * 32>>>(q, f0, f1, h0, h1, out, M);
}

// round 3
// speedup vs baseline: 1.4255x; 1.4255x over previous
#include <cuda_runtime.h>
#include <cstdint>

// VoxelHashTable: 2-level hash-grid trilinear interpolation.
// Inputs (metadata order):
//   d_in[0] query_pts (M,3) f32
//   d_in[1] feats0    (n0,32) f32
//   d_in[2] feats1    (n1,32) f32
//   d_in[3] h2v0      (2^20) i32
//   d_in[4] h2v1      (2^20) i32
// Output: (M, 64) f32  — [level0 32 | level1 32]
//
// Warp layout (1 warp = 1 query):
//   level  = lane>>4          (lanes 0-15 -> level0, 16-31 -> level1)
//   g      = lane>>3          group 0..3 ; corner-half chalf = g&1 (x-offset bit)
//   s      = lane&7           channel chunk: floats 4s..4s+3
//   Hash lookups on lanes with (lane&8)==0: corner = lane&7, level = lane>>4.
//   Gather loop t=0..3: each 8-lane group loads one 128B feature row (float4/lane)
//   for corner r = chalf*4 + t of its level, accumulates w*feat.
//   Final: shfl_xor(8) merges the two corner-halves; lanes (lane&8)==0 store float4.

#define TSIZE_MASK ((1 << 20) - 1)

// PRIMES % 2^20 (exact):
#define PMX 455773
#define PMY 475301
#define PMZ 655287

__global__ __launch_bounds__(256) void voxel_hash_kernel(
    const float* __restrict__ q,
    const float* __restrict__ f0,
    const float* __restrict__ f1,
    const int* __restrict__ h0,
    const int* __restrict__ h1,
    float* __restrict__ out,
    int M)
{
    const int warp = (blockIdx.x * blockDim.x + threadIdx.x) >> 5;
    const int lane = threadIdx.x & 31;
    if (warp >= M) return;

    const int level = lane >> 4;     // this lane's resolution level
    const int chalf = (lane >> 3) & 1; // corner-half: x-offset bit
    const int s     = lane & 7;      // channel chunk (4 floats)

    // Broadcast loads of the query point (same address across warp).
    const float qx = __ldg(q + warp * 3 + 0);
    const float qy = __ldg(q + warp * 3 + 1);
    const float qz = __ldg(q + warp * 3 + 2);

    // Only this lane's level. 0.24f == float32(0.12*2.0) exactly.
    const float res = level ? 0.24f : 0.12f;
    const float sx = __fdiv_rn(qx, res);
    const float sy = __fdiv_rn(qy, res);
    const float sz = __fdiv_rn(qz, res);

    const float bx = floorf(sx), by = floorf(sy), bz = floorf(sz);
    const float fx = sx - bx, fy = sy - by, fz = sz - bz;
    const int ix = (int)bx, iy = (int)by, iz = (int)bz;

    // Hash lookup: lanes 0-7 (level0, corner=lane) and 16-23 (level1, corner=lane&7).
    int vidx = -1;
    {
        const int c  = lane & 7;
        const int cx = ix + ((c >> 2) & 1);
        const int cy = iy + ((c >> 1) & 1);
        const int cz = iz + (c & 1);
        const unsigned hv =
            ((unsigned)(cx * PMX + cy * PMY + cz * PMZ)) & TSIZE_MASK;
        const int* __restrict__ hp = level ? h1 : h0;
        if ((lane & 8) == 0) vidx = __ldg(hp + hv);
    }

    // Lane-constant weight pieces.
    const float wx  = chalf ? fx : 1.0f - fx;
    const float gy0 = 1.0f - fy;
    const float gz0 = 1.0f - fz;
    const float* __restrict__ fp = level ? f1 : f0;

    float4 acc = make_float4(0.f, 0.f, 0.f, 0.f);

    #pragma unroll
    for (int t = 0; t < 4; ++t) {
        // corner r = chalf*4 + t ; its hash value lives on lane level*16 + r
        const int src = (level << 4) + (chalf << 2) + t;
        const int v = __shfl_sync(0xFFFFFFFFu, vidx, src);

        // ((wx*wy)*wz) multiply order matches reference prod(axis=2).
        const float w = wx * ((t & 2) ? fy : gy0) * ((t & 1) ? fz : gz0);

        if (v >= 0) {
            const float4 f = __ldg((const float4*)(fp + (size_t)v * 32 + s * 4));
            acc.x = fmaf(f.x, w, acc.x);
            acc.y = fmaf(f.y, w, acc.y);
            acc.z = fmaf(f.z, w, acc.z);
            acc.w = fmaf(f.w, w, acc.w);
        }
    }

    // Merge the two corner-halves (groups differing in bit 3).
    acc.x += __shfl_xor_sync(0xFFFFFFFFu, acc.x, 8);
    acc.y += __shfl_xor_sync(0xFFFFFFFFu, acc.y, 8);
    acc.z += __shfl_xor_sync(0xFFFFFFFFu, acc.z, 8);
    acc.w += __shfl_xor_sync(0xFFFFFFFFu, acc.w, 8);

    // Lanes 0-7 write level0 channels, lanes 16-23 write level1 channels.
    if ((lane & 8) == 0) {
        *(float4*)(out + (size_t)warp * 64 + level * 32 + s * 4) = acc;
    }
}

extern "C" void kernel_launch(void* const* d_in, const int* in_sizes, int n_in,
                              void* d_out, int out_size)
{
    const float* q  = (const float*)d_in[0];
    const float* f0 = (const float*)d_in[1];
    const float* f1 = (const float*)d_in[2];
    const int*   h0 = (const int*)d_in[3];
    const int*   h1 = (const int*)d_in[4];
    float* out = (float*)d_out;

    const int M = in_sizes[0] / 3;

    const int warps_per_block = 8;
    const int blocks = (M + warps_per_block - 1) / warps_per_block;
    voxel_hash_kernel<<<blocks, warps_per_block * 32>>>(q, f0, f1, h0, h1, out, M);
}

// round 4
// speedup vs baseline: 1.5674x; 1.0995x over previous
#include <cuda_runtime.h>
#include <cstdint>

// VoxelHashTable: 2-level hash-grid trilinear interpolation.
// Inputs (metadata order):
//   d_in[0] query_pts (M,3) f32
//   d_in[1] feats0    (n0,32) f32
//   d_in[2] feats1    (n1,32) f32
//   d_in[3] h2v0      (2^20) i32
//   d_in[4] h2v1      (2^20) i32
// Output: (M, 64) f32  — [level0 32 | level1 32]
//
// Warp layout (1 warp = 2 queries):
//   half  = lane>>4        which query of the pair
//   level = (lane>>3)&1    resolution level this lane serves
//   s     = lane&7         channel chunk (floats 4s..4s+3)
// Hash: every lane does ONE lookup for (its query, its level, corner = lane&7).
// Gather: 8 iterations over corner t; each 8-lane group loads one 128B feature
// row (LDG.128/lane) for (its query, its level, corner t) and accumulates w*f.
// Each lane's accumulator is exactly output[query*64 + level*32 + 4s..4s+3]:
// no merge shuffles; the warp store is 512B fully-coalesced STG.128.

#define TSIZE_MASK ((1 << 20) - 1)

// PRIMES % 2^20 (exact):
#define PMX 455773
#define PMY 475301
#define PMZ 655287

__global__ __launch_bounds__(256) void voxel_hash_kernel(
    const float* __restrict__ q,
    const float* __restrict__ f0,
    const float* __restrict__ f1,
    const int* __restrict__ h0,
    const int* __restrict__ h1,
    float* __restrict__ out,
    int M)
{
    const int pair = (blockIdx.x * blockDim.x + threadIdx.x) >> 5;
    const int lane = threadIdx.x & 31;

    const int half  = lane >> 4;        // which query of the pair
    const int level = (lane >> 3) & 1;  // this lane's resolution level
    const int s     = lane & 7;         // float4 chunk within the 32-dim feature

    int qidx = pair * 2 + half;
    const bool active = qidx < M;
    if (__all_sync(0xFFFFFFFFu, !active)) return;
    if (qidx >= M) qidx = M - 1;        // clamp; store is guarded below

    // Per-lane query point (2 distinct addresses per warp -> 1-2 wavefronts each).
    const float qx = __ldg(q + qidx * 3 + 0);
    const float qy = __ldg(q + qidx * 3 + 1);
    const float qz = __ldg(q + qidx * 3 + 2);

    // This lane's level only. 0.24f == float32(0.12*2.0) exactly.
    const float res = level ? 0.24f : 0.12f;
    const float sx = __fdiv_rn(qx, res);
    const float sy = __fdiv_rn(qy, res);
    const float sz = __fdiv_rn(qz, res);

    const float bx = floorf(sx), by = floorf(sy), bz = floorf(sz);
    const float fx = sx - bx, fy = sy - by, fz = sz - bz;
    const int ix = (int)bx, iy = (int)by, iz = (int)bz;

    // Hash lookup: corner = lane&7 of (this query, this level). All 32 lanes.
    int vidx;
    {
        const int cx = ix + ((lane >> 2) & 1);
        const int cy = iy + ((lane >> 1) & 1);
        const int cz = iz + (lane & 1);
        const unsigned hv =
            ((unsigned)(cx * PMX + cy * PMY + cz * PMZ)) & TSIZE_MASK;
        const int* __restrict__ hp = level ? h1 : h0;
        vidx = __ldg(hp + hv);
    }

    const float gx = 1.0f - fx;
    const float gy = 1.0f - fy;
    const float gz = 1.0f - fz;
    const float* __restrict__ fp = level ? f1 : f0;

    // Source lane base for this (query, level)'s 8 hash results.
    const int src_base = lane & 0x18;   // (half<<4) | (level<<3)

    float4 acc = make_float4(0.f, 0.f, 0.f, 0.f);

    #pragma unroll
    for (int t = 0; t < 8; ++t) {
        const int v = __shfl_sync(0xFFFFFFFFu, vidx, src_base + t);

        // ((wx*wy)*wz) multiply order matches reference prod(axis=2).
        const float w = ((t & 4) ? fx : gx) *
                        ((t & 2) ? fy : gy) *
                        ((t & 1) ? fz : gz);

        if (v >= 0) {
            const float4 f = __ldg((const float4*)(fp + (size_t)v * 32 + s * 4));
            acc.x = fmaf(f.x, w, acc.x);
            acc.y = fmaf(f.y, w, acc.y);
            acc.z = fmaf(f.z, w, acc.z);
            acc.w = fmaf(f.w, w, acc.w);
        }
    }

    // Each lane writes its own (query, level, chunk): 512B contiguous per warp.
    if (active) {
        *(float4*)(out + (size_t)qidx * 64 + level * 32 + s * 4) = acc;
    }
}

extern "C" void kernel_launch(void* const* d_in, const int* in_sizes, int n_in,
                              void* d_out, int out_size)
{
    const float* q  = (const float*)d_in[0];
    const float* f0 = (const float*)d_in[1];
    const float* f1 = (const float*)d_in[2];
    const int*   h0 = (const int*)d_in[3];
    const int*   h1 = (const int*)d_in[4];
    float* out = (float*)d_out;

    const int M = in_sizes[0] / 3;
    const int pairs = (M + 1) / 2;

    const int warps_per_block = 8;
    const int blocks = (pairs + warps_per_block - 1) / warps_per_block;
    voxel_hash_kernel<<<blocks, warps_per_block * 32>>>(q, f0, f1, h0, h1, out, M);
}

// round 5
// speedup vs baseline: 1.6849x; 1.0750x over previous
#include <cuda_runtime.h>
#include <cstdint>

// VoxelHashTable: 2-level hash-grid trilinear interpolation.
// Inputs (metadata order):
//   d_in[0] query_pts (M,3) f32
//   d_in[1] feats0    (n0,32) f32
//   d_in[2] feats1    (n1,32) f32
//   d_in[3] h2v0      (2^20) i32
//   d_in[4] h2v1      (2^20) i32
// Output: (M, 64) f32  — [level0 32 | level1 32]
//
// Warp layout (1 warp = 2 queries):
//   half  = lane>>4        which query of the pair
//   level = (lane>>3)&1    resolution level this lane serves
//   s     = lane&7         channel chunk (floats 4s..4s+3)
// Hash: every lane does ONE lookup for (its query, its level, corner = lane&7).
// Gather: 8 iterations over corner t; each 8-lane group loads one 128B feature
// row (LDG.128/lane) for (its query, its level, corner t) and accumulates w*f.
// Each lane's accumulator is exactly output[query*64 + level*32 + 4s..4s+3]:
// the warp store is 512B fully-coalesced STG.128.
//
// __launch_bounds__(256, 8): force regs <= 32 for full occupancy — the kernel
// is L1-wavefront bound with a load->shfl->load dependency chain, so resident
// warps are what hide the L2-hit latency.

#define TSIZE_MASK ((1 << 20) - 1)

// PRIMES % 2^20 (exact):
#define PMX 455773
#define PMY 475301
#define PMZ 655287

__global__ __launch_bounds__(256, 8) void voxel_hash_kernel(
    const float* __restrict__ q,
    const float* __restrict__ f0,
    const float* __restrict__ f1,
    const int* __restrict__ h0,
    const int* __restrict__ h1,
    float* __restrict__ out,
    int M)
{
    const int pair = (blockIdx.x * blockDim.x + threadIdx.x) >> 5;
    const int lane = threadIdx.x & 31;

    const int half  = lane >> 4;        // which query of the pair
    const int level = (lane >> 3) & 1;  // this lane's resolution level
    const int s     = lane & 7;         // float4 chunk within the 32-dim feature

    int qidx = pair * 2 + half;
    const bool active = qidx < M;
    if (qidx >= M) qidx = M - 1;        // clamp; store guarded below

    // Per-lane query point (2 distinct rows per warp, usually 1-2 lines).
    const float qx = __ldg(q + qidx * 3 + 0);
    const float qy = __ldg(q + qidx * 3 + 1);
    const float qz = __ldg(q + qidx * 3 + 2);

    // This lane's level only. 0.24f == float32(0.12*2.0) exactly.
    const float res = level ? 0.24f : 0.12f;
    const float sx = __fdiv_rn(qx, res);
    const float sy = __fdiv_rn(qy, res);
    const float sz = __fdiv_rn(qz, res);

    const float bx = floorf(sx), by = floorf(sy), bz = floorf(sz);
    const float fx = sx - bx, fy = sy - by, fz = sz - bz;

    // Hash lookup: corner = lane&7 of (this query, this level). All 32 lanes.
    int vidx;
    {
        const int cx = (int)bx + ((lane >> 2) & 1);
        const int cy = (int)by + ((lane >> 1) & 1);
        const int cz = (int)bz + (lane & 1);
        const unsigned hv =
            ((unsigned)(cx * PMX + cy * PMY + cz * PMZ)) & TSIZE_MASK;
        const int* __restrict__ hp = level ? h1 : h0;
        vidx = __ldg(hp + hv);
    }

    const float gx = 1.0f - fx;
    const float gy = 1.0f - fy;
    const float gz = 1.0f - fz;
    const float* __restrict__ fp = (level ? f1 : f0) + s * 4;

    // Source lane base for this (query, level)'s 8 hash results.
    const int src_base = lane & 0x18;   // (half<<4) | (level<<3)

    float4 acc = make_float4(0.f, 0.f, 0.f, 0.f);

    #pragma unroll
    for (int t = 0; t < 8; ++t) {
        const int v = __shfl_sync(0xFFFFFFFFu, vidx, src_base + t);

        // ((wx*wy)*wz) multiply order matches reference prod(axis=2).
        const float w = ((t & 4) ? fx : gx) *
                        ((t & 2) ? fy : gy) *
                        ((t & 1) ? fz : gz);

        if (v >= 0) {
            const float4 f = __ldg((const float4*)(fp + (size_t)v * 32));
            acc.x = fmaf(f.x, w, acc.x);
            acc.y = fmaf(f.y, w, acc.y);
            acc.z = fmaf(f.z, w, acc.z);
            acc.w = fmaf(f.w, w, acc.w);
        }
    }

    // Each lane writes its own (query, level, chunk): 512B contiguous per warp.
    if (active) {
        *(float4*)(out + (size_t)qidx * 64 + level * 32 + s * 4) = acc;
    }
}

extern "C" void kernel_launch(void* const* d_in, const int* in_sizes, int n_in,
                              void* d_out, int out_size)
{
    const float* q  = (const float*)d_in[0];
    const float* f0 = (const float*)d_in[1];
    const float* f1 = (const float*)d_in[2];
    const int*   h0 = (const int*)d_in[3];
    const int*   h1 = (const int*)d_in[4];
    float* out = (float*)d_out;

    const int M = in_sizes[0] / 3;
    const int pairs = (M + 1) / 2;

    const int warps_per_block = 8;
    const int blocks = (pairs + warps_per_block - 1) / warps_per_block;
    voxel_hash_kernel<<<blocks, warps_per_block * 32>>>(q, f0, f1, h0, h1, out, M);
}